// round 9
// baseline (speedup 1.0000x reference)
#include <cuda_runtime.h>
#include <cstdint>

#define SCORE_THRESH 0.05f
#define IOU_THRESH   0.5f
#define KTOP 1000
#define KPAD 1024
#define MAXDET 100
#define MAX_A (1 << 18)
#define NBLK 148
#define NTHR 1024
#define M2CAP 4096
#define DSMEM_MID 40960
#define DSMEM_NMS 131072

// ---------------- device scratch ----------------
__device__ __align__(16) unsigned g_key[MAX_A];
__device__ unsigned            g_ties[MAX_A];           // fallback path only
__device__ unsigned long long  g_cand[KPAD];
__device__ __align__(16) unsigned long long g_m2buf[M2CAP];
__device__ int                 g_m2Cnt;
__device__ unsigned short      g_perm[KPAD];
__device__ unsigned            g_hist0[2048];
__device__ unsigned            g_hist1[2048];
__device__ unsigned            g_hist2[1024];
__device__ int                 g_candCount;
__device__ int                 g_tieCount;
__device__ __align__(16) unsigned g_maskR[KPAD * 32];
__device__ float               g_rscore[KPAD];
__device__ unsigned            g_ridx[KPAD];
__device__ __align__(16) float g_rbox[KPAD * 4];
__device__ unsigned            g_barGen;
__device__ unsigned            g_barCnt;

__device__ __forceinline__ unsigned f2key(float f) {
    unsigned b = __float_as_uint(f);
    return (b & 0x80000000u) ? ~b : (b | 0x80000000u);
}
__device__ __forceinline__ float key2f(unsigned k) {
    unsigned b = (k & 0x80000000u) ? (k ^ 0x80000000u) : ~k;
    return __uint_as_float(b);
}

__device__ __forceinline__ void gsync() {
    __syncthreads();
    if (threadIdx.x == 0) {
        volatile unsigned* vg = &g_barGen;
        unsigned gen = *vg;
        __threadfence();
        if (atomicAdd(&g_barCnt, 1u) == NBLK - 1) {
            atomicExch(&g_barCnt, 0u);
            __threadfence();
            atomicAdd(&g_barGen, 1u);
        } else {
            while (*vg == gen) __nanosleep(32);
        }
        __threadfence();
    }
    __syncthreads();
}

// ======= kernel A: per-anchor score + pass-0 histogram (R7 version) ========
__global__ void __launch_bounds__(256, 8)
k_score(const float* __restrict__ cls, int A, int C) {
    __shared__ unsigned sh[2048];
    for (int i = threadIdx.x; i < 2048; i += 256) sh[i] = 0;
    __syncthreads();
    int lane = threadIdx.x & 31;
    int gw = blockIdx.x * 8 + (threadIdx.x >> 5);
    int nw = gridDim.x * 8;
    if (C == 80) {
        const float4* p = (const float4*)cls;
        for (int a0 = gw * 8; a0 < A; a0 += nw * 8) {
            float m[8];
            #pragma unroll
            for (int r = 0; r < 8; ++r) m[r] = 0.0f;     // scores >= 0
            if (lane < 20) {
                #pragma unroll
                for (int r = 0; r < 8; ++r) {
                    int a = a0 + r;
                    if (a < A) {
                        float4 v = p[(size_t)a * 20 + lane];
                        m[r] = fmaxf(fmaxf(v.x, v.y), fmaxf(v.z, v.w));
                    }
                }
            }
            #pragma unroll
            for (int r = 0; r < 8; ++r) {
                unsigned u = __reduce_max_sync(0xFFFFFFFFu, __float_as_uint(m[r]));
                m[r] = __uint_as_float(u);
            }
            if (lane < 8) {
                float mv;
                switch (lane) {
                    case 0: mv = m[0]; break;
                    case 1: mv = m[1]; break;
                    case 2: mv = m[2]; break;
                    case 3: mv = m[3]; break;
                    case 4: mv = m[4]; break;
                    case 5: mv = m[5]; break;
                    case 6: mv = m[6]; break;
                    default: mv = m[7]; break;
                }
                int a = a0 + lane;
                bool valid = (a < A);
                unsigned k = f2key(mv > SCORE_THRESH ? mv : -1.0f);
                if (valid) g_key[a] = k;
                unsigned bin = valid ? (k >> 21) : (2048u + (unsigned)lane);
                unsigned mm = __match_any_sync(0xFFu, bin);
                if (valid && lane == (__ffs(mm) - 1))
                    atomicAdd(&sh[bin], (unsigned)__popc(mm));
            }
        }
    } else {
        for (int a = gw; a < A; a += nw) {
            float mm2 = -3.402823466e38f;
            const float* row = cls + (size_t)a * C;
            for (int c = lane; c < C; c += 32) mm2 = fmaxf(mm2, row[c]);
            #pragma unroll
            for (int o = 16; o; o >>= 1) mm2 = fmaxf(mm2, __shfl_down_sync(0xFFFFFFFFu, mm2, o));
            if (lane == 0) {
                unsigned k = f2key(mm2 > SCORE_THRESH ? mm2 : -1.0f);
                g_key[a] = k;
                atomicAdd(&sh[k >> 21], 1u);
            }
        }
    }
    __syncthreads();
    for (int i = threadIdx.x; i < 2048; i += 256) {
        unsigned v = sh[i];
        if (v) atomicAdd(&g_hist0[i], v);
    }
}

// block-local radix select, 3 barriers (warp-shfl suffix scans)
__device__ void block_select(const unsigned* hist, int bins, unsigned krem,
                             unsigned* wsm, int* psel,
                             unsigned* pdig, unsigned* pkrem) {
    int t = threadIdx.x, lane = t & 31, w = t >> 5;
    int per = bins >> 10;
    unsigned c0 = hist[t * per];
    unsigned c1 = (per == 2) ? hist[t * per + 1] : 0u;
    unsigned tot = c0 + c1;
    if (t == 0) *psel = -1;
    unsigned s = tot;
    #pragma unroll
    for (int off = 1; off < 32; off <<= 1) {
        unsigned v = __shfl_down_sync(0xFFFFFFFFu, s, off);
        if (lane + off < 32) s += v;
    }
    if (lane == 0) wsm[w] = s;
    __syncthreads();
    if (t < 32) {
        unsigned wv = wsm[t];
        unsigned ws = wv;
        #pragma unroll
        for (int off = 1; off < 32; off <<= 1) {
            unsigned v = __shfl_down_sync(0xFFFFFFFFu, ws, off);
            if (t + off < 32) ws += v;
        }
        wsm[t] = ws - wv;
    }
    __syncthreads();
    unsigned suffExcl = wsm[w] + (s - tot);
    int best = -1; unsigned accAt = 0, cntAt = 0;
    unsigned acc = suffExcl;
    if (per == 2) {
        acc += c1;
        if (acc >= krem) { best = 2 * t + 1; accAt = acc; cntAt = c1; }
        else { acc += c0; if (acc >= krem) { best = 2 * t; accAt = acc; cntAt = c0; } }
    } else {
        acc += c0;
        if (acc >= krem) { best = t; accAt = acc; cntAt = c0; }
    }
    if (best >= 0) atomicMax(psel, best);
    __syncthreads();
    if (best >= 0 && best == *psel) {
        *pdig = (unsigned)best;
        *pkrem = krem - (accAt - cntAt);
    }
    __syncthreads();
}

// ======== kernel B: selects + sweeps + scand build + rank + decode + mask ==
__global__ void __launch_bounds__(NTHR, 1)
k_mid(const float* __restrict__ reg, const float* __restrict__ anc,
      const int* __restrict__ pih, const int* __restrict__ piw, int A) {
    extern __shared__ unsigned char dsm[];
    __shared__ unsigned s_wsm[32];
    __shared__ int      s_sel;
    __shared__ unsigned s_dig;
    __shared__ unsigned s_krem;
    __shared__ unsigned s_total;

    const int tid = threadIdx.x;
    const int bid = blockIdx.x;
    const int A4 = A >> 2;
    const int Atail = A4 << 2;

    unsigned pref0, krem1;
    {   // B0: select0 + sweep1 (hist1 for bin0 + collect strictly-above keys)
        block_select(g_hist0, 2048, KTOP, s_wsm, &s_sel, &s_dig, &s_krem);
        pref0 = s_dig; krem1 = s_krem;
        unsigned* sh = (unsigned*)dsm;
        for (int i = tid; i < 2048; i += NTHR) sh[i] = 0;
        __syncthreads();
        const uint4* kp = (const uint4*)g_key;
        for (int i = bid * NTHR + tid; i < A4; i += NBLK * NTHR) {
            uint4 kv = kp[i];
            unsigned base = (unsigned)(i << 2);
            #pragma unroll
            for (int c = 0; c < 4; ++c) {
                unsigned k = (c == 0) ? kv.x : (c == 1) ? kv.y : (c == 2) ? kv.z : kv.w;
                unsigned d = k >> 21;
                if (d == pref0) atomicAdd(&sh[(k >> 10) & 0x7FFu], 1u);
                else if (d > pref0) {
                    int p = atomicAdd(&g_candCount, 1);
                    g_cand[p] = ((unsigned long long)k << 32) | (0xFFFFFFFFu - (base + c));
                }
            }
        }
        if (bid == 0) {
            for (int a = Atail + tid; a < A; a += NTHR) {
                unsigned k = g_key[a];
                unsigned d = k >> 21;
                if (d == pref0) atomicAdd(&sh[(k >> 10) & 0x7FFu], 1u);
                else if (d > pref0) {
                    int p = atomicAdd(&g_candCount, 1);
                    g_cand[p] = ((unsigned long long)k << 32) | (0xFFFFFFFFu - (unsigned)a);
                }
            }
        }
        __syncthreads();
        for (int i = tid; i < 2048; i += NTHR) {
            unsigned v = sh[i];
            if (v) atomicAdd(&g_hist1[i], v);
        }
    }
    gsync();  // 1

    unsigned pref21, krem2;
    {   // B1: select1 + sweep2 (hist2 + collect above-in-bin0 + spill pref21 matchers)
        block_select(g_hist1, 2048, krem1, s_wsm, &s_sel, &s_dig, &s_krem);
        unsigned dig1 = s_dig;
        pref21 = (pref0 << 11) | dig1; krem2 = s_krem;
        unsigned* sh = (unsigned*)dsm;
        for (int i = tid; i < 1024; i += NTHR) sh[i] = 0;
        __syncthreads();
        const uint4* kp = (const uint4*)g_key;
        for (int i = bid * NTHR + tid; i < A4; i += NBLK * NTHR) {
            uint4 kv = kp[i];
            unsigned base = (unsigned)(i << 2);
            #pragma unroll
            for (int c = 0; c < 4; ++c) {
                unsigned k = (c == 0) ? kv.x : (c == 1) ? kv.y : (c == 2) ? kv.z : kv.w;
                if ((k >> 21) == pref0) {
                    unsigned d = (k >> 10) & 0x7FFu;
                    if (d == dig1) {
                        atomicAdd(&sh[k & 0x3FFu], 1u);
                        int p = atomicAdd(&g_m2Cnt, 1);
                        if (p < M2CAP)
                            g_m2buf[p] = ((unsigned long long)k << 32) | (0xFFFFFFFFu - (base + c));
                    } else if (d > dig1) {
                        int p = atomicAdd(&g_candCount, 1);
                        g_cand[p] = ((unsigned long long)k << 32) | (0xFFFFFFFFu - (base + c));
                    }
                }
            }
        }
        if (bid == 0) {
            for (int a = Atail + tid; a < A; a += NTHR) {
                unsigned k = g_key[a];
                if ((k >> 21) == pref0) {
                    unsigned d = (k >> 10) & 0x7FFu;
                    if (d == dig1) {
                        atomicAdd(&sh[k & 0x3FFu], 1u);
                        int p = atomicAdd(&g_m2Cnt, 1);
                        if (p < M2CAP)
                            g_m2buf[p] = ((unsigned long long)k << 32) | (0xFFFFFFFFu - (unsigned)a);
                    } else if (d > dig1) {
                        int p = atomicAdd(&g_candCount, 1);
                        g_cand[p] = ((unsigned long long)k << 32) | (0xFFFFFFFFu - (unsigned)a);
                    }
                }
            }
        }
        __syncthreads();
        for (int i = tid; i < 1024; i += NTHR) {
            unsigned v = sh[i];
            if (v) atomicAdd(&g_hist2[i], v);
        }
    }
    gsync();  // 2

    unsigned long long* scand = (unsigned long long*)dsm;            // 8KB @0
    {   // B2: select2 + redundant scand build (buffer path) + rank-by-count
        block_select(g_hist2, 1024, krem2, s_wsm, &s_sel, &s_dig, &s_krem);
        unsigned pivot = (pref21 << 10) | s_dig;
        int CA = g_candCount;
        int M2 = g_m2Cnt;

        if (M2 <= M2CAP) {
            unsigned long long* sm2 = (unsigned long long*)(dsm + 8192);  // 32KB
            for (int i = tid; i < M2; i += NTHR) sm2[i] = g_m2buf[i];
            scand[tid] = (tid < CA) ? g_cand[tid]
                       : ((tid >= KTOP) ? (unsigned long long)(KPAD - tid) : 0ULL);
            __syncthreads();
            // prefix scan (buffer order) over "candidate" flags: deterministic
            int base = tid * 4;
            unsigned long long e[4];
            int nloc = 0;
            unsigned tc = 0;
            #pragma unroll
            for (int j = 0; j < 4; ++j) {
                int ii = base + j;
                if (ii < M2) {
                    e[j] = sm2[ii];
                    ++nloc;
                    if ((unsigned)(e[j] >> 32) > pivot) ++tc;
                }
            }
            {   // block exclusive scan of tc
                int lane = tid & 31, w = tid >> 5;
                unsigned inc = tc;
                #pragma unroll
                for (int off = 1; off < 32; off <<= 1) {
                    unsigned v = __shfl_up_sync(0xFFFFFFFFu, inc, off);
                    if (lane >= off) inc += v;
                }
                if (lane == 31) s_wsm[w] = inc;
                __syncthreads();
                if (tid < 32) {
                    unsigned wv = s_wsm[tid];
                    unsigned wi = wv;
                    #pragma unroll
                    for (int off = 1; off < 32; off <<= 1) {
                        unsigned v = __shfl_up_sync(0xFFFFFFFFu, wi, off);
                        if (tid >= off) wi += v;
                    }
                    s_wsm[tid] = wi - wv;   // exclusive warp offset
                    if (tid == 31) s_total = wi;
                }
                __syncthreads();
                unsigned excl = s_wsm[w] + inc - tc;
                int p = CA + (int)excl;
                #pragma unroll
                for (int j = 0; j < 4; ++j) {
                    if (j < nloc && (unsigned)(e[j] >> 32) > pivot)
                        scand[p++] = e[j];
                }
            }
            __syncthreads();
            int candTot = CA + (int)s_total;
            int need = KTOP - candTot;
            if (need > 0) {
                // ties: entries with key == pivot; pick `need` largest u64
                // (== smallest anchor index). rank by counting larger ties.
                #pragma unroll
                for (int j = 0; j < 4; ++j) {
                    if (j < nloc && (unsigned)(e[j] >> 32) == pivot) {
                        unsigned long long mine = e[j];
                        int rank = 0;
                        for (int i2 = 0; i2 < M2; ++i2) {
                            unsigned long long o = sm2[i2];
                            rank += ((unsigned)(o >> 32) == pivot && o > mine);
                        }
                        if (rank < need) scand[candTot + rank] = mine;
                    }
                }
            }
            __syncthreads();
        } else {
            // fallback: classic compact sweep + tie-fill (rare)
            if (bid == 0 && tid == 0) { g_candCount = CA; g_tieCount = 0; }
            gsync();
            const uint4* kp = (const uint4*)g_key;
            for (int i = bid * NTHR + tid; i < A4; i += NBLK * NTHR) {
                uint4 kv = kp[i];
                unsigned base = (unsigned)(i << 2);
                #pragma unroll
                for (int c = 0; c < 4; ++c) {
                    unsigned k = (c == 0) ? kv.x : (c == 1) ? kv.y : (c == 2) ? kv.z : kv.w;
                    if ((k >> 10) == pref21) {
                        unsigned a = base + (unsigned)c;
                        if ((k & 0x3FFu) > s_dig) {
                            int p = atomicAdd(&g_candCount, 1);
                            g_cand[p] = ((unsigned long long)k << 32) | (0xFFFFFFFFu - a);
                        } else if ((k & 0x3FFu) == s_dig) {
                            int t2 = atomicAdd(&g_tieCount, 1);
                            g_ties[t2] = a;
                        }
                    }
                }
            }
            if (bid == 0) {
                for (int a = Atail + tid; a < A; a += NTHR) {
                    unsigned k = g_key[a];
                    if ((k >> 10) == pref21) {
                        if ((k & 0x3FFu) > s_dig) {
                            int p = atomicAdd(&g_candCount, 1);
                            g_cand[p] = ((unsigned long long)k << 32) | (0xFFFFFFFFu - (unsigned)a);
                        } else if ((k & 0x3FFu) == s_dig) {
                            int t2 = atomicAdd(&g_tieCount, 1);
                            g_ties[t2] = (unsigned)a;
                        }
                    }
                }
            }
            gsync();
            int CAt = g_candCount;
            int T = g_tieCount;
            int need = KTOP - CAt;
            unsigned long long pivKey = ((unsigned long long)pivot << 32);
            scand[tid] = (tid < CAt) ? g_cand[tid]
                       : ((tid >= KTOP) ? (unsigned long long)(KPAD - tid) : 0ULL);
            __syncthreads();
            if (need > 0) {
                for (int t2 = tid; t2 < T; t2 += NTHR) {
                    unsigned v = g_ties[t2];
                    int rank = 0;
                    for (int i2 = 0; i2 < T; ++i2) rank += (g_ties[i2] < v);
                    if (rank < need) scand[CAt + rank] = pivKey | (0xFFFFFFFFu - v);
                }
            }
            __syncthreads();
        }
        // rank-by-counting → g_perm
        #pragma unroll
        for (int j = 0; j < 7; ++j) {
            int s = bid + j * NBLK;
            bool cmp = (s < KPAD) ? (scand[tid] > scand[s]) : false;
            int rank = __syncthreads_count(cmp);
            if (tid == 0 && s < KPAD) g_perm[rank] = (unsigned short)s;
        }
    }
    gsync();  // 3

    {   // B3: decode in rank order (redundant) + triangle mask rows + cleanup
        float4* sbox  = (float4*)(dsm + 8192);
        float*  sarea = (float*)(dsm + 24576);
        // clear state for next graph replay
        for (int i = bid * NTHR + tid; i < 2048; i += NBLK * NTHR) g_hist0[i] = 0;
        for (int i = bid * NTHR + tid; i < 2048; i += NBLK * NTHR) g_hist1[i] = 0;
        for (int i = bid * NTHR + tid; i < 1024; i += NBLK * NTHR) g_hist2[i] = 0;
        if (bid == 0 && tid == 0) { g_candCount = 0; g_tieCount = 0; g_m2Cnt = 0; }

        int slot = g_perm[tid];
        unsigned long long ck = scand[slot];
        float score; float4 box; unsigned idx = 0;
        if (ck >= (1ULL << 32)) {
            unsigned key = (unsigned)(ck >> 32);
            idx = 0xFFFFFFFFu - (unsigned)(ck & 0xFFFFFFFFu);
            score = key2f(key);
            float4 a4 = ((const float4*)anc)[idx];
            float4 r4 = ((const float4*)reg)[idx];
            float aw = a4.z - a4.x, ah = a4.w - a4.y;
            float acx = a4.x + 0.5f * aw, acy = a4.y + 0.5f * ah;
            float pcx = acx + (r4.x * 0.1f) * aw;
            float pcy = acy + (r4.y * 0.1f) * ah;
            float pw = expf(r4.z * 0.2f) * aw;
            float ph = expf(r4.w * 0.2f) * ah;
            float W = (float)(*piw);
            float H = (float)(*pih);
            box.x = fminf(fmaxf(pcx - 0.5f * pw, 0.f), W);
            box.y = fminf(fmaxf(pcy - 0.5f * ph, 0.f), H);
            box.z = fminf(fmaxf(pcx + 0.5f * pw, 0.f), W);
            box.w = fminf(fmaxf(pcy + 0.5f * ph, 0.f), H);
        } else {
            score = -1.0f;
            box.x = box.y = box.z = box.w = 0.f;
        }
        sbox[tid] = box;
        sarea[tid] = fmaxf(box.z - box.x, 0.f) * fmaxf(box.w - box.y, 0.f);
        if (bid == 0) {
            g_rscore[tid] = score;
            g_ridx[tid] = idx;
            ((float4*)g_rbox)[tid] = box;
        }
        __syncthreads();
        float4 cb = sbox[tid];
        float  ca = sarea[tid];
        for (int r = bid; r < KPAD; r += NBLK) {
            bool sup = false;
            if (tid > r) {
                float4 rb = sbox[r];
                float  ra = sarea[r];
                float xx1 = fmaxf(rb.x, cb.x);
                float yy1 = fmaxf(rb.y, cb.y);
                float xx2 = fminf(rb.z, cb.z);
                float yy2 = fminf(rb.w, cb.w);
                float inter = fmaxf(xx2 - xx1, 0.f) * fmaxf(yy2 - yy1, 0.f);
                float denom = ra + ca - inter + 1e-8f;
                sup = inter > IOU_THRESH * denom;
            }
            unsigned ball = __ballot_sync(0xFFFFFFFFu, sup);
            if ((tid & 31) == 0) g_maskR[r * 32 + (tid >> 5)] = ball;
        }
    }
}

// ======== kernel C: NMS scan + final outputs (single block) ================
__global__ void __launch_bounds__(NTHR, 1)
k_nms(const float* __restrict__ cls, float* __restrict__ out, int C) {
    extern __shared__ unsigned char dsm[];
    __shared__ int s_dc;
    __shared__ int s_det[128];
    int tid = threadIdx.x;
    unsigned* smask = (unsigned*)dsm;
    {
        const uint4* gm = (const uint4*)g_maskR;
        uint4* sm4 = (uint4*)smask;
        for (int i = tid; i < KPAD * 8; i += NTHR) sm4[i] = gm[i];
    }
    int myvalid = (g_rscore[tid] > SCORE_THRESH) ? 1 : 0;
    int nvalid = __syncthreads_count(myvalid);
    if (tid < 32) {
        int base = tid * 32;
        unsigned alive;
        if (nvalid >= base + 32)      alive = 0xFFFFFFFFu;
        else if (nvalid <= base)      alive = 0u;
        else                          alive = (1u << (nvalid - base)) - 1u;
        unsigned rem = 0;
        int dc = 0;
        while (dc < MAXDET) {
            unsigned av = alive & ~rem;
            unsigned ball = __ballot_sync(0xFFFFFFFFu, av != 0u);
            if (!ball) break;
            int grp = __ffs(ball) - 1;
            unsigned gav = __shfl_sync(0xFFFFFFFFu, av, grp);
            int b = __ffs(gav) - 1;
            int rank = (grp << 5) + b;
            if (tid == 0) s_det[dc] = rank;
            dc++;
            if (tid == grp) alive &= ~(1u << b);
            rem |= smask[rank * 32 + tid];
        }
        if (tid == 0) s_dc = dc;
    }
    __syncthreads();
    int dc = s_dc;
    int lane = tid & 31;
    int w = tid >> 5;
    for (int d = w; d < MAXDET; d += 32) {
        if (d < dc) {
            int rank = s_det[d];
            unsigned idx = g_ridx[rank];
            const float* row = cls + (size_t)idx * C;
            float bv = -3.402823466e38f; int bi = 0;
            for (int c = lane; c < C; c += 32) {
                float v = row[c];
                if (v > bv) { bv = v; bi = c; }
            }
            #pragma unroll
            for (int o = 16; o; o >>= 1) {
                float ov = __shfl_down_sync(0xFFFFFFFFu, bv, o);
                int   oi = __shfl_down_sync(0xFFFFFFFFu, bi, o);
                if (ov > bv || (ov == bv && oi < bi)) { bv = ov; bi = oi; }
            }
            if (lane == 0) {
                out[d] = g_rscore[rank];
                out[100 + d] = (float)bi;
                out[200 + 4 * d + 0] = g_rbox[4 * rank + 0];
                out[200 + 4 * d + 1] = g_rbox[4 * rank + 1];
                out[200 + 4 * d + 2] = g_rbox[4 * rank + 2];
                out[200 + 4 * d + 3] = g_rbox[4 * rank + 3];
            }
        } else if (lane == 0) {
            out[d] = 0.0f;
            out[100 + d] = -1.0f;
            out[200 + 4 * d + 0] = 0.0f; out[200 + 4 * d + 1] = 0.0f;
            out[200 + 4 * d + 2] = 0.0f; out[200 + 4 * d + 3] = 0.0f;
        }
    }
}

// ---------------- host launcher ----------------
extern "C" void kernel_launch(void* const* d_in, const int* in_sizes, int n_in,
                              void* d_out, int out_size) {
    const float* cls = (const float*)d_in[0];
    const float* reg = (const float*)d_in[1];
    const float* anc = (const float*)d_in[2];
    const int* ih = (const int*)d_in[3];
    const int* iw = (const int*)d_in[4];

    int A = in_sizes[1] / 4;
    int C = (A > 0) ? (in_sizes[0] / A) : 80;
    float* out = (float*)d_out;
    (void)out_size; (void)n_in;

    cudaFuncSetAttribute(k_mid, cudaFuncAttributeMaxDynamicSharedMemorySize, DSMEM_MID);
    cudaFuncSetAttribute(k_nms, cudaFuncAttributeMaxDynamicSharedMemorySize, DSMEM_NMS);

    k_score<<<1184, 256>>>(cls, A, C);
    k_mid<<<NBLK, NTHR, DSMEM_MID>>>(reg, anc, ih, iw, A);
    k_nms<<<1, NTHR, DSMEM_NMS>>>(cls, out, C);
}

// round 10
// speedup vs baseline: 1.1187x; 1.1187x over previous
#include <cuda_runtime.h>
#include <cstdint>

#define SCORE_THRESH 0.05f
#define IOU_THRESH   0.5f
#define KTOP 1000
#define KPAD 1024
#define MAXDET 100
#define MAX_A (1 << 18)
#define NBLK 148
#define NTHR 1024
#define DSMEM_FIN 131072

// ---------------- device scratch ----------------
__device__ __align__(16) unsigned g_key[MAX_A];
__device__ unsigned            g_ties[MAX_A];
__device__ unsigned long long  g_cand[KPAD];
__device__ unsigned short      g_perm[KPAD];
__device__ unsigned            g_hist0[2048];
__device__ unsigned            g_hist1[2048];
__device__ unsigned            g_hist2[1024];
__device__ int                 g_candCount;
__device__ int                 g_tieCount;
__device__ __align__(16) unsigned g_maskR[KPAD * 32];
__device__ float               g_rscore[KPAD];
__device__ unsigned            g_ridx[KPAD];
__device__ __align__(16) float g_rbox[KPAD * 4];
__device__ unsigned            g_barGen;
__device__ unsigned            g_barCnt;

__device__ __forceinline__ unsigned f2key(float f) {
    unsigned b = __float_as_uint(f);
    return (b & 0x80000000u) ? ~b : (b | 0x80000000u);
}
__device__ __forceinline__ float key2f(unsigned k) {
    unsigned b = (k & 0x80000000u) ? (k ^ 0x80000000u) : ~k;
    return __uint_as_float(b);
}

__device__ __forceinline__ void gsync() {
    __syncthreads();
    if (threadIdx.x == 0) {
        volatile unsigned* vg = &g_barGen;
        unsigned gen = *vg;
        __threadfence();
        if (atomicAdd(&g_barCnt, 1u) == NBLK - 1) {
            atomicExch(&g_barCnt, 0u);
            __threadfence();
            atomicAdd(&g_barGen, 1u);
        } else {
            while (*vg == gen) __nanosleep(32);
        }
        __threadfence();
    }
    __syncthreads();
}

// ======= kernel A: per-anchor score + pass-0 histogram (R7, 15.1us) ========
__global__ void __launch_bounds__(256, 8)
k_score(const float* __restrict__ cls, int A, int C) {
    __shared__ unsigned sh[2048];
    for (int i = threadIdx.x; i < 2048; i += 256) sh[i] = 0;
    __syncthreads();
    int lane = threadIdx.x & 31;
    int gw = blockIdx.x * 8 + (threadIdx.x >> 5);
    int nw = gridDim.x * 8;
    if (C == 80) {
        const float4* p = (const float4*)cls;
        for (int a0 = gw * 8; a0 < A; a0 += nw * 8) {
            float m[8];
            #pragma unroll
            for (int r = 0; r < 8; ++r) m[r] = 0.0f;     // scores >= 0
            if (lane < 20) {
                #pragma unroll
                for (int r = 0; r < 8; ++r) {
                    int a = a0 + r;
                    if (a < A) {
                        float4 v = p[(size_t)a * 20 + lane];
                        m[r] = fmaxf(fmaxf(v.x, v.y), fmaxf(v.z, v.w));
                    }
                }
            }
            #pragma unroll
            for (int r = 0; r < 8; ++r) {
                unsigned u = __reduce_max_sync(0xFFFFFFFFu, __float_as_uint(m[r]));
                m[r] = __uint_as_float(u);
            }
            if (lane < 8) {
                float mv;
                switch (lane) {
                    case 0: mv = m[0]; break;
                    case 1: mv = m[1]; break;
                    case 2: mv = m[2]; break;
                    case 3: mv = m[3]; break;
                    case 4: mv = m[4]; break;
                    case 5: mv = m[5]; break;
                    case 6: mv = m[6]; break;
                    default: mv = m[7]; break;
                }
                int a = a0 + lane;
                bool valid = (a < A);
                unsigned k = f2key(mv > SCORE_THRESH ? mv : -1.0f);
                if (valid) g_key[a] = k;
                unsigned bin = valid ? (k >> 21) : (2048u + (unsigned)lane);
                unsigned mm = __match_any_sync(0xFFu, bin);
                if (valid && lane == (__ffs(mm) - 1))
                    atomicAdd(&sh[bin], (unsigned)__popc(mm));
            }
        }
    } else {
        for (int a = gw; a < A; a += nw) {
            float mm2 = -3.402823466e38f;
            const float* row = cls + (size_t)a * C;
            for (int c = lane; c < C; c += 32) mm2 = fmaxf(mm2, row[c]);
            #pragma unroll
            for (int o = 16; o; o >>= 1) mm2 = fmaxf(mm2, __shfl_down_sync(0xFFFFFFFFu, mm2, o));
            if (lane == 0) {
                unsigned k = f2key(mm2 > SCORE_THRESH ? mm2 : -1.0f);
                g_key[a] = k;
                atomicAdd(&sh[k >> 21], 1u);
            }
        }
    }
    __syncthreads();
    for (int i = threadIdx.x; i < 2048; i += 256) {
        unsigned v = sh[i];
        if (v) atomicAdd(&g_hist0[i], v);
    }
}

// block-local radix select, 3 barriers (warp-shfl suffix scans)
__device__ void block_select(const unsigned* hist, int bins, unsigned krem,
                             unsigned* wsm, int* psel,
                             unsigned* pdig, unsigned* pkrem) {
    int t = threadIdx.x, lane = t & 31, w = t >> 5;
    int per = bins >> 10;
    unsigned c0 = hist[t * per];
    unsigned c1 = (per == 2) ? hist[t * per + 1] : 0u;
    unsigned tot = c0 + c1;
    if (t == 0) *psel = -1;
    unsigned s = tot;
    #pragma unroll
    for (int off = 1; off < 32; off <<= 1) {
        unsigned v = __shfl_down_sync(0xFFFFFFFFu, s, off);
        if (lane + off < 32) s += v;
    }
    if (lane == 0) wsm[w] = s;
    __syncthreads();
    if (t < 32) {
        unsigned wv = wsm[t];
        unsigned ws = wv;
        #pragma unroll
        for (int off = 1; off < 32; off <<= 1) {
            unsigned v = __shfl_down_sync(0xFFFFFFFFu, ws, off);
            if (t + off < 32) ws += v;
        }
        wsm[t] = ws - wv;
    }
    __syncthreads();
    unsigned suffExcl = wsm[w] + (s - tot);
    int best = -1; unsigned accAt = 0, cntAt = 0;
    unsigned acc = suffExcl;
    if (per == 2) {
        acc += c1;
        if (acc >= krem) { best = 2 * t + 1; accAt = acc; cntAt = c1; }
        else { acc += c0; if (acc >= krem) { best = 2 * t; accAt = acc; cntAt = c0; } }
    } else {
        acc += c0;
        if (acc >= krem) { best = t; accAt = acc; cntAt = c0; }
    }
    if (best >= 0) atomicMax(psel, best);
    __syncthreads();
    if (best >= 0 && best == *psel) {
        *pdig = (unsigned)best;
        *pkrem = krem - (accAt - cntAt);
    }
    __syncthreads();
}

// == kernel B: selects + compact + rank + decode + mask + NMS + outputs =====
__global__ void __launch_bounds__(NTHR, 1)
k_fin(const float* __restrict__ cls, const float* __restrict__ reg,
      const float* __restrict__ anc, const int* __restrict__ pih,
      const int* __restrict__ piw, float* __restrict__ out, int A, int C) {
    extern __shared__ unsigned char dsm[];
    __shared__ unsigned s_wsm[32];
    __shared__ int      s_sel;
    __shared__ unsigned s_dig;
    __shared__ unsigned s_krem;
    __shared__ int      s_dc;
    __shared__ int      s_det[128];

    const int tid = threadIdx.x;
    const int bid = blockIdx.x;
    const int A4 = A >> 2;
    const int Atail = A4 << 2;

    unsigned pref0, krem1;
    {   // B0: select0 + pass-1 histogram
        block_select(g_hist0, 2048, KTOP, s_wsm, &s_sel, &s_dig, &s_krem);
        pref0 = s_dig; krem1 = s_krem;
        unsigned* sh = (unsigned*)dsm;
        for (int i = tid; i < 2048; i += NTHR) sh[i] = 0;
        __syncthreads();
        const uint4* kp = (const uint4*)g_key;
        for (int i = bid * NTHR + tid; i < A4; i += NBLK * NTHR) {
            uint4 k = kp[i];
            if ((k.x >> 21) == pref0) atomicAdd(&sh[(k.x >> 10) & 0x7FFu], 1u);
            if ((k.y >> 21) == pref0) atomicAdd(&sh[(k.y >> 10) & 0x7FFu], 1u);
            if ((k.z >> 21) == pref0) atomicAdd(&sh[(k.z >> 10) & 0x7FFu], 1u);
            if ((k.w >> 21) == pref0) atomicAdd(&sh[(k.w >> 10) & 0x7FFu], 1u);
        }
        if (bid == 0) {
            for (int a = Atail + tid; a < A; a += NTHR) {
                unsigned k = g_key[a];
                if ((k >> 21) == pref0) atomicAdd(&sh[(k >> 10) & 0x7FFu], 1u);
            }
        }
        __syncthreads();
        for (int i = tid; i < 2048; i += NTHR) {
            unsigned v = sh[i];
            if (v) atomicAdd(&g_hist1[i], v);
        }
    }
    gsync();  // 1

    unsigned pref21, krem2;
    {   // B1: select1 + pass-2 histogram
        block_select(g_hist1, 2048, krem1, s_wsm, &s_sel, &s_dig, &s_krem);
        pref21 = (pref0 << 11) | s_dig; krem2 = s_krem;
        unsigned* sh = (unsigned*)dsm;
        for (int i = tid; i < 1024; i += NTHR) sh[i] = 0;
        __syncthreads();
        const uint4* kp = (const uint4*)g_key;
        for (int i = bid * NTHR + tid; i < A4; i += NBLK * NTHR) {
            uint4 k = kp[i];
            if ((k.x >> 10) == pref21) atomicAdd(&sh[k.x & 0x3FFu], 1u);
            if ((k.y >> 10) == pref21) atomicAdd(&sh[k.y & 0x3FFu], 1u);
            if ((k.z >> 10) == pref21) atomicAdd(&sh[k.z & 0x3FFu], 1u);
            if ((k.w >> 10) == pref21) atomicAdd(&sh[k.w & 0x3FFu], 1u);
        }
        if (bid == 0) {
            for (int a = Atail + tid; a < A; a += NTHR) {
                unsigned k = g_key[a];
                if ((k >> 10) == pref21) atomicAdd(&sh[k & 0x3FFu], 1u);
            }
        }
        __syncthreads();
        for (int i = tid; i < 1024; i += NTHR) {
            unsigned v = sh[i];
            if (v) atomicAdd(&g_hist2[i], v);
        }
    }
    gsync();  // 2

    unsigned pivot;
    {   // B2: select2 + compact
        block_select(g_hist2, 1024, krem2, s_wsm, &s_sel, &s_dig, &s_krem);
        pivot = (pref21 << 10) | s_dig;
        const uint4* kp = (const uint4*)g_key;
        for (int i = bid * NTHR + tid; i < A4; i += NBLK * NTHR) {
            uint4 kv = kp[i];
            unsigned base = (unsigned)(i << 2);
            #pragma unroll
            for (int c = 0; c < 4; ++c) {
                unsigned k = (c == 0) ? kv.x : (c == 1) ? kv.y : (c == 2) ? kv.z : kv.w;
                unsigned a = base + (unsigned)c;
                if (k > pivot) {
                    int p = atomicAdd(&g_candCount, 1);
                    g_cand[p] = ((unsigned long long)k << 32) | (0xFFFFFFFFu - a);
                } else if (k == pivot) {
                    int t2 = atomicAdd(&g_tieCount, 1);
                    g_ties[t2] = a;
                }
            }
        }
        if (bid == 0) {
            for (int a = Atail + tid; a < A; a += NTHR) {
                unsigned k = g_key[a];
                if (k > pivot) {
                    int p = atomicAdd(&g_candCount, 1);
                    g_cand[p] = ((unsigned long long)k << 32) | (0xFFFFFFFFu - (unsigned)a);
                } else if (k == pivot) {
                    int t2 = atomicAdd(&g_tieCount, 1);
                    g_ties[t2] = (unsigned)a;
                }
            }
        }
    }
    gsync();  // 3

    unsigned long long* scand = (unsigned long long*)dsm;            // 8KB
    {   // B3: tie-fill + distributed rank-by-counting
        unsigned* sties = (unsigned*)(dsm + 8192);
        int CA = g_candCount;
        int T  = g_tieCount;
        int need = KTOP - CA;
        unsigned long long pivKey = ((unsigned long long)pivot << 32);

        // clear histograms for next graph replay
        for (int i = bid * NTHR + tid; i < 2048; i += NBLK * NTHR) g_hist0[i] = 0;
        for (int i = bid * NTHR + tid; i < 2048; i += NBLK * NTHR) g_hist1[i] = 0;
        for (int i = bid * NTHR + tid; i < 1024; i += NBLK * NTHR) g_hist2[i] = 0;

        scand[tid] = (tid < CA) ? g_cand[tid]
                   : ((tid >= KTOP) ? (unsigned long long)(KPAD - tid) : 0ULL);
        if (T <= 2048) {
            if (tid < T) sties[tid] = g_ties[tid];
            if (tid + 1024 < T) sties[tid + 1024] = g_ties[tid + 1024];
            __syncthreads();
            for (int t = tid; t < T; t += NTHR) {
                unsigned v = sties[t];
                int rank = 0;
                for (int i = 0; i < T; ++i) rank += (sties[i] < v);
                if (rank < need)
                    scand[CA + rank] = pivKey | (0xFFFFFFFFu - v);
            }
            __syncthreads();
        } else {
            unsigned* red = (unsigned*)(dsm + 8192);
            unsigned prev = 0; bool first = true;
            for (int r2 = 0; r2 < need; ++r2) {
                unsigned lm = 0xFFFFFFFFu;
                for (int i = tid; i < T; i += NTHR) {
                    unsigned v = g_ties[i];
                    if ((first || v > prev) && v < lm) lm = v;
                }
                red[tid] = lm;
                __syncthreads();
                for (int st = 512; st; st >>= 1) {
                    if (tid < st) red[tid] = min(red[tid], red[tid + st]);
                    __syncthreads();
                }
                prev = red[0]; first = false;
                if (tid == 0) scand[CA + r2] = pivKey | (0xFFFFFFFFu - prev);
                __syncthreads();
            }
        }
        #pragma unroll
        for (int j = 0; j < 7; ++j) {
            int s = bid + j * NBLK;
            bool cmp = (s < KPAD) ? (scand[tid] > scand[s]) : false;
            int rank = __syncthreads_count(cmp);
            if (tid == 0 && s < KPAD) g_perm[rank] = (unsigned short)s;
        }
    }
    gsync();  // 4

    {   // B4: decode in rank order (redundant) + triangle mask rows
        float4* sbox  = (float4*)(dsm + 16384);
        float*  sarea = (float*)(dsm + 32768);
        int slot = g_perm[tid];
        unsigned long long ck = scand[slot];
        float score; float4 box; unsigned idx = 0;
        if (ck >= (1ULL << 32)) {
            unsigned key = (unsigned)(ck >> 32);
            idx = 0xFFFFFFFFu - (unsigned)(ck & 0xFFFFFFFFu);
            score = key2f(key);
            float4 a4 = ((const float4*)anc)[idx];
            float4 r4 = ((const float4*)reg)[idx];
            float aw = a4.z - a4.x, ah = a4.w - a4.y;
            float acx = a4.x + 0.5f * aw, acy = a4.y + 0.5f * ah;
            float pcx = acx + (r4.x * 0.1f) * aw;
            float pcy = acy + (r4.y * 0.1f) * ah;
            float pw = expf(r4.z * 0.2f) * aw;
            float ph = expf(r4.w * 0.2f) * ah;
            float W = (float)(*piw);
            float H = (float)(*pih);
            box.x = fminf(fmaxf(pcx - 0.5f * pw, 0.f), W);
            box.y = fminf(fmaxf(pcy - 0.5f * ph, 0.f), H);
            box.z = fminf(fmaxf(pcx + 0.5f * pw, 0.f), W);
            box.w = fminf(fmaxf(pcy + 0.5f * ph, 0.f), H);
        } else {
            score = -1.0f;
            box.x = box.y = box.z = box.w = 0.f;
        }
        sbox[tid] = box;
        sarea[tid] = fmaxf(box.z - box.x, 0.f) * fmaxf(box.w - box.y, 0.f);
        if (bid == 0) {
            g_rscore[tid] = score;
            g_ridx[tid] = idx;
            ((float4*)g_rbox)[tid] = box;
        }
        __syncthreads();
        float4 cb = sbox[tid];
        float  ca = sarea[tid];
        for (int r = bid; r < KPAD; r += NBLK) {
            bool sup = false;
            if (tid > r) {
                float4 rb = sbox[r];
                float  ra = sarea[r];
                float xx1 = fmaxf(rb.x, cb.x);
                float yy1 = fmaxf(rb.y, cb.y);
                float xx2 = fminf(rb.z, cb.z);
                float yy2 = fminf(rb.w, cb.w);
                float inter = fmaxf(xx2 - xx1, 0.f) * fmaxf(yy2 - yy1, 0.f);
                float denom = ra + ca - inter + 1e-8f;
                sup = inter > IOU_THRESH * denom;
            }
            unsigned ball = __ballot_sync(0xFFFFFFFFu, sup);
            if ((tid & 31) == 0) g_maskR[r * 32 + (tid >> 5)] = ball;
        }
    }
    gsync();  // 5

    if (bid != 0) return;

    {   // B5 (block 0): NMS scan + outputs + counter reset (race-free here)
        unsigned* smask = (unsigned*)dsm;
        {
            const uint4* gm = (const uint4*)g_maskR;
            uint4* sm4 = (uint4*)smask;
            for (int i = tid; i < KPAD * 8; i += NTHR) sm4[i] = gm[i];
        }
        int myvalid = (g_rscore[tid] > SCORE_THRESH) ? 1 : 0;
        int nvalid = __syncthreads_count(myvalid);   // valid = rank prefix
        if (tid < 32) {
            int base = tid * 32;
            unsigned alive;
            if (nvalid >= base + 32)      alive = 0xFFFFFFFFu;
            else if (nvalid <= base)      alive = 0u;
            else                          alive = (1u << (nvalid - base)) - 1u;
            unsigned rem = 0;
            int dc = 0;
            while (dc < MAXDET) {
                unsigned av = alive & ~rem;
                unsigned ball = __ballot_sync(0xFFFFFFFFu, av != 0u);
                if (!ball) break;
                int grp = __ffs(ball) - 1;
                unsigned gav = __shfl_sync(0xFFFFFFFFu, av, grp);
                int b = __ffs(gav) - 1;
                int rank = (grp << 5) + b;
                if (tid == 0) s_det[dc] = rank;
                dc++;
                if (tid == grp) alive &= ~(1u << b);
                rem |= smask[rank * 32 + tid];
            }
            if (tid == 0) s_dc = dc;
        }
        __syncthreads();
        int dc = s_dc;
        int lane = tid & 31;
        int w = tid >> 5;
        for (int d = w; d < MAXDET; d += 32) {
            if (d < dc) {
                int rank = s_det[d];
                unsigned idx = g_ridx[rank];
                const float* row = cls + (size_t)idx * C;
                float bv = -3.402823466e38f; int bi = 0;
                for (int c = lane; c < C; c += 32) {
                    float v = row[c];
                    if (v > bv) { bv = v; bi = c; }
                }
                #pragma unroll
                for (int o = 16; o; o >>= 1) {
                    float ov = __shfl_down_sync(0xFFFFFFFFu, bv, o);
                    int   oi = __shfl_down_sync(0xFFFFFFFFu, bi, o);
                    if (ov > bv || (ov == bv && oi < bi)) { bv = ov; bi = oi; }
                }
                if (lane == 0) {
                    out[d] = g_rscore[rank];
                    out[100 + d] = (float)bi;
                    out[200 + 4 * d + 0] = g_rbox[4 * rank + 0];
                    out[200 + 4 * d + 1] = g_rbox[4 * rank + 1];
                    out[200 + 4 * d + 2] = g_rbox[4 * rank + 2];
                    out[200 + 4 * d + 3] = g_rbox[4 * rank + 3];
                }
            } else if (lane == 0) {
                out[d] = 0.0f;
                out[100 + d] = -1.0f;
                out[200 + 4 * d + 0] = 0.0f; out[200 + 4 * d + 1] = 0.0f;
                out[200 + 4 * d + 2] = 0.0f; out[200 + 4 * d + 3] = 0.0f;
            }
        }
        if (tid == 0) { g_candCount = 0; g_tieCount = 0; }
    }
}

// ---------------- host launcher ----------------
extern "C" void kernel_launch(void* const* d_in, const int* in_sizes, int n_in,
                              void* d_out, int out_size) {
    const float* cls = (const float*)d_in[0];
    const float* reg = (const float*)d_in[1];
    const float* anc = (const float*)d_in[2];
    const int* ih = (const int*)d_in[3];
    const int* iw = (const int*)d_in[4];

    int A = in_sizes[1] / 4;
    int C = (A > 0) ? (in_sizes[0] / A) : 80;
    float* out = (float*)d_out;
    (void)out_size; (void)n_in;

    cudaFuncSetAttribute(k_fin, cudaFuncAttributeMaxDynamicSharedMemorySize, DSMEM_FIN);

    k_score<<<1184, 256>>>(cls, A, C);
    k_fin<<<NBLK, NTHR, DSMEM_FIN>>>(cls, reg, anc, ih, iw, out, A, C);
}